// round 2
// baseline (speedup 1.0000x reference)
#include <cuda_runtime.h>
#include <math.h>

// Problem constants
#define BN_  8192   // batch
#define TN_  658    // seq len (also final output features)
#define IN_  7      // input features
#define D1_  1024
#define D2_  512
#define D3_  128
#define T4PAD_ 768  // w4T padded N (658 -> 768 = 6*128)

// ---------------- scratch (static __device__, no allocation) ----------------
__device__ float g_hsT[TN_ * BN_];      // RNN outputs, [t][b]  (A^T for GEMM1)
__device__ float g_c1 [D1_ * BN_];      // [n][m] transposed activations
__device__ float g_c2 [D2_ * BN_];
__device__ float g_c3 [D3_ * BN_];
__device__ float g_w1T[TN_  * D1_];     // [K=658][N=1024]
__device__ float g_w2T[D1_ * D2_];      // [K=1024][N=512]
__device__ float g_w3T[D2_ * D3_];      // [K=512][N=128]
__device__ float g_w4T[D3_ * T4PAD_];   // [K=128][Npad=768], zero padded

// ---------------- weight transpose (+pad) ----------------
__global__ void wtrans_kernel(const float* __restrict__ W, float* __restrict__ WT,
                              int N, int K, int Npad)
{
    int idx = blockIdx.x * blockDim.x + threadIdx.x;
    int total = K * Npad;
    if (idx >= total) return;
    int k = idx / Npad;
    int n = idx - k * Npad;
    WT[idx] = (n < N) ? W[n * K + k] : 0.0f;
}

// ---------------- RNN: scalar recurrence per batch element ----------------
__global__ void rnn_kernel(const float* __restrict__ x,
                           const float* __restrict__ h0,
                           const float* __restrict__ Wih,
                           const float* __restrict__ Whh,
                           const float* __restrict__ bih,
                           const float* __restrict__ bhh,
                           float* __restrict__ hsT,
                           float* __restrict__ hidden /* may be null */)
{
    int b = blockIdx.x * blockDim.x + threadIdx.x;
    if (b >= BN_) return;

    float w0 = Wih[0], w1 = Wih[1], w2 = Wih[2], w3 = Wih[3];
    float w4 = Wih[4], w5 = Wih[5], w6 = Wih[6];
    float a    = Whh[0];
    float bias = bih[0] + bhh[0];

    float h = h0[b];
    const float* xp = x + (size_t)b * (TN_ * IN_);

    #pragma unroll 4
    for (int t = 0; t < TN_; t++) {
        const float* p = xp + t * IN_;
        float xw = bias;
        xw = fmaf(p[0], w0, xw);
        xw = fmaf(p[1], w1, xw);
        xw = fmaf(p[2], w2, xw);
        xw = fmaf(p[3], w3, xw);
        xw = fmaf(p[4], w4, xw);
        xw = fmaf(p[5], w5, xw);
        xw = fmaf(p[6], w6, xw);
        h = tanhf(fmaf(a, h, xw));
        hsT[t * BN_ + b] = h;   // coalesced across threads
    }
    if (hidden) hidden[b] = h;
}

// ---------------- tiled fp32 GEMM ----------------
// Computes C[m,n] = sum_k AT[k,m] * WT[k,n] + bias[n]   (optionally relu)
// AT: [K, M] row stride M.  WT: [K, Npad] row stride Npad (zero-padded).
// If TOUT: stores C transposed, CT[n*M + m]  (requires N % 128 == 0 for full tiles).
// Else:    stores row-major C[m*N + n] with n < N guard.
template<bool RELU, bool TOUT>
__global__ __launch_bounds__(256, 2)
void gemm_tt_kernel(const float* __restrict__ AT, const float* __restrict__ WT,
                    const float* __restrict__ bias, float* __restrict__ C,
                    int M, int N, int Npad, int K)
{
    const int BM = 128, BN = 128, BK = 8;
    __shared__ float As[BK][BM];
    __shared__ float Bs[BK][BN];

    int m0 = blockIdx.y * BM;
    int n0 = blockIdx.x * BN;
    int tid = threadIdx.x;
    int tx = tid & 15;    // 0..15 -> n micro tile
    int ty = tid >> 4;    // 0..15 -> m micro tile

    float acc[8][8];
    #pragma unroll
    for (int i = 0; i < 8; i++)
        #pragma unroll
        for (int j = 0; j < 8; j++) acc[i][j] = 0.0f;

    int lk = tid >> 5;          // 0..7
    int lv = (tid & 31) << 2;   // 0,4,...,124

    for (int k0 = 0; k0 < K; k0 += BK) {
        int k = k0 + lk;
        float4 av, bv;
        if (k < K) {
            av = *(const float4*)(AT + (size_t)k * M    + m0 + lv);
            bv = *(const float4*)(WT + (size_t)k * Npad + n0 + lv);
        } else {
            av = make_float4(0.f, 0.f, 0.f, 0.f);
            bv = av;
        }
        *(float4*)(&As[lk][lv]) = av;
        *(float4*)(&Bs[lk][lv]) = bv;
        __syncthreads();

        #pragma unroll
        for (int kk = 0; kk < BK; kk++) {
            float a[8], bb[8];
            *(float4*)(a)      = *(const float4*)(&As[kk][ty * 8]);
            *(float4*)(a + 4)  = *(const float4*)(&As[kk][ty * 8 + 4]);
            *(float4*)(bb)     = *(const float4*)(&Bs[kk][tx * 8]);
            *(float4*)(bb + 4) = *(const float4*)(&Bs[kk][tx * 8 + 4]);
            #pragma unroll
            for (int i = 0; i < 8; i++)
                #pragma unroll
                for (int j = 0; j < 8; j++)
                    acc[i][j] = fmaf(a[i], bb[j], acc[i][j]);
        }
        __syncthreads();
    }

    if (TOUT) {
        // transposed store: CT[n][m], fully in-bounds (N % 128 == 0)
        #pragma unroll
        for (int j = 0; j < 8; j++) {
            int n = n0 + tx * 8 + j;
            float bb = bias[n];
            float v[8];
            #pragma unroll
            for (int i = 0; i < 8; i++) {
                float t = acc[i][j] + bb;
                v[i] = RELU ? fmaxf(t, 0.0f) : t;
            }
            float* cp = C + (size_t)n * M + m0 + ty * 8;
            *(float4*)(cp)     = *(float4*)(v);
            *(float4*)(cp + 4) = *(float4*)(v + 4);
        }
    } else {
        // row-major store with n guard
        #pragma unroll
        for (int i = 0; i < 8; i++) {
            int m = m0 + ty * 8 + i;
            #pragma unroll
            for (int j = 0; j < 8; j++) {
                int n = n0 + tx * 8 + j;
                if (n < N) {
                    float t = acc[i][j] + bias[n];
                    C[(size_t)m * N + n] = RELU ? fmaxf(t, 0.0f) : t;
                }
            }
        }
    }
}

// ---------------- launcher ----------------
extern "C" void kernel_launch(void* const* d_in, const int* in_sizes, int n_in,
                              void* d_out, int out_size)
{
    const float* x    = (const float*)d_in[0];
    const float* h0   = (const float*)d_in[1];
    const float* Wih  = (const float*)d_in[2];
    const float* Whh  = (const float*)d_in[3];
    const float* bih  = (const float*)d_in[4];
    const float* bhh  = (const float*)d_in[5];
    const float* w1   = (const float*)d_in[6];
    const float* b1   = (const float*)d_in[7];
    const float* w2   = (const float*)d_in[8];
    const float* b2   = (const float*)d_in[9];
    const float* w3   = (const float*)d_in[10];
    const float* b3   = (const float*)d_in[11];
    const float* w4   = (const float*)d_in[12];
    const float* b4   = (const float*)d_in[13];
    float* out = (float*)d_out;

    float *hsT, *c1, *c2, *c3, *w1T, *w2T, *w3T, *w4T;
    cudaGetSymbolAddress((void**)&hsT, g_hsT);
    cudaGetSymbolAddress((void**)&c1,  g_c1);
    cudaGetSymbolAddress((void**)&c2,  g_c2);
    cudaGetSymbolAddress((void**)&c3,  g_c3);
    cudaGetSymbolAddress((void**)&w1T, g_w1T);
    cudaGetSymbolAddress((void**)&w2T, g_w2T);
    cudaGetSymbolAddress((void**)&w3T, g_w3T);
    cudaGetSymbolAddress((void**)&w4T, g_w4T);

    // weight transposes (small)
    {
        int t1 = TN_  * D1_;   wtrans_kernel<<<(t1 + 255) / 256, 256>>>(w1, w1T, D1_, TN_,  D1_);
        int t2 = D1_ * D2_;    wtrans_kernel<<<(t2 + 255) / 256, 256>>>(w2, w2T, D2_, D1_, D2_);
        int t3 = D2_ * D3_;    wtrans_kernel<<<(t3 + 255) / 256, 256>>>(w3, w3T, D3_, D2_, D3_);
        int t4 = D3_ * T4PAD_; wtrans_kernel<<<(t4 + 255) / 256, 256>>>(w4, w4T, TN_, D3_, T4PAD_);
    }

    // RNN. hidden output goes after the [B,T] block if the harness expects it.
    float* hidden = (out_size >= BN_ * TN_ + BN_) ? (out + (size_t)BN_ * TN_) : nullptr;
    rnn_kernel<<<BN_ / 64, 64>>>(x, h0, Wih, Whh, bih, bhh, hsT, hidden);

    // GEMM chain (all A^T / W^T, coalesced)
    dim3 blk(256);
    // L1: [8192,658] x [658,1024] -> c1T
    gemm_tt_kernel<true,  true ><<<dim3(D1_ / 128, BN_ / 128), blk>>>(hsT, w1T, b1, c1, BN_, D1_, D1_, TN_);
    // L2: -> c2T
    gemm_tt_kernel<true,  true ><<<dim3(D2_ / 128, BN_ / 128), blk>>>(c1,  w2T, b2, c2, BN_, D2_, D2_, D1_);
    // L3: -> c3T
    gemm_tt_kernel<true,  true ><<<dim3(D3_ / 128, BN_ / 128), blk>>>(c2,  w3T, b3, c3, BN_, D3_, D3_, D2_);
    // L4: -> out [B, T] row-major (n < 658 guard)
    gemm_tt_kernel<false, false><<<dim3(T4PAD_ / 128, BN_ / 128), blk>>>(c3, w4T, b4, out, BN_, TN_, T4PAD_, D3_);
}

// round 4
// speedup vs baseline: 1.9661x; 1.9661x over previous
#include <cuda_runtime.h>
#include <math.h>
#include <stdint.h>

// ---------------- problem constants ----------------
#define BN_  8192   // batch (GEMM M)
#define TN_  658    // seq len / final out features
#define TP_  672    // K-pad for layer1 (21 * 32)
#define IN_  7
#define D1_  1024
#define D2_  512
#define D3_  128
#define N4P_ 768    // w4 N padded (658 -> 768)

// ---------------- scratch ----------------
__device__ float g_hs [(size_t)BN_ * TP_];   // [B, 672] tf32-rounded, zero padded
__device__ float g_c1 [(size_t)BN_ * D1_];   // tf32-rounded activations
__device__ float g_c2 [(size_t)BN_ * D2_];
__device__ float g_c3 [(size_t)BN_ * D3_];
__device__ float g_w1c[D1_ * TP_];           // [1024, 672] tf32, K-padded
__device__ float g_w2c[D2_ * D1_];           // [512, 1024] tf32
__device__ float g_w3c[D3_ * D2_];           // [128, 512] tf32
__device__ float g_w4c[N4P_ * D3_];          // [768, 128] tf32, N-padded

// ---------------- helpers ----------------
__device__ __forceinline__ uint32_t smem_u32(const void* p) {
    uint32_t a;
    asm("{ .reg .u64 t; cvta.to.shared.u64 t, %1; cvt.u32.u64 %0, t; }" : "=r"(a) : "l"(p));
    return a;
}
__device__ __forceinline__ float cvt_tf32f(float x) {
    uint32_t u; asm("cvt.rna.tf32.f32 %0, %1;" : "=r"(u) : "f"(x));
    return __uint_as_float(u);
}
#define CP16(sa, ga) asm volatile("cp.async.cg.shared.global [%0], [%1], 16;" :: "r"(sa), "l"(ga))
#define CP_COMMIT()  asm volatile("cp.async.commit_group;" ::: "memory")
#define CP_WAIT0()   asm volatile("cp.async.wait_group 0;" ::: "memory")
#define CP_WAIT1()   asm volatile("cp.async.wait_group 1;" ::: "memory")

__device__ __forceinline__ void mma_tf32(float* d, const uint32_t* a, const uint32_t* b) {
    asm volatile(
        "mma.sync.aligned.m16n8k8.row.col.f32.tf32.tf32.f32 "
        "{%0,%1,%2,%3}, {%4,%5,%6,%7}, {%8,%9}, {%0,%1,%2,%3};"
        : "+f"(d[0]), "+f"(d[1]), "+f"(d[2]), "+f"(d[3])
        : "r"(a[0]), "r"(a[1]), "r"(a[2]), "r"(a[3]), "r"(b[0]), "r"(b[1]));
}

// ---------------- weight pad + tf32 round ----------------
__global__ void wprep_kernel(const float* __restrict__ src, float* __restrict__ dst,
                             int srcN, int srcK, int dstN, int dstK)
{
    int idx = blockIdx.x * blockDim.x + threadIdx.x;
    if (idx >= dstN * dstK) return;
    int n = idx / dstK, k = idx - n * dstK;
    dst[idx] = (n < srcN && k < srcK) ? cvt_tf32f(src[n * srcK + k]) : 0.0f;
}

// ---------------- RNN: scalar recurrence ----------------
__global__ void rnn_kernel(const float* __restrict__ x,
                           const float* __restrict__ h0,
                           const float* __restrict__ Wih,
                           const float* __restrict__ Whh,
                           const float* __restrict__ bih,
                           const float* __restrict__ bhh,
                           float* __restrict__ hs,
                           float* __restrict__ hidden)
{
    int b = blockIdx.x * blockDim.x + threadIdx.x;
    if (b >= BN_) return;

    float w0 = Wih[0], w1 = Wih[1], w2 = Wih[2], w3 = Wih[3];
    float w4 = Wih[4], w5 = Wih[5], w6 = Wih[6];
    float a = Whh[0];
    float bias = bih[0] + bhh[0];

    float h = h0[b];
    const float* xp = x + (size_t)b * (TN_ * IN_);
    float* hp = hs + (size_t)b * TP_;

    #pragma unroll 2
    for (int t = 0; t < TN_; t++) {
        const float* p = xp + t * IN_;
        float xw = bias;
        xw = fmaf(p[0], w0, xw);
        xw = fmaf(p[1], w1, xw);
        xw = fmaf(p[2], w2, xw);
        xw = fmaf(p[3], w3, xw);
        xw = fmaf(p[4], w4, xw);
        xw = fmaf(p[5], w5, xw);
        xw = fmaf(p[6], w6, xw);
        h = tanhf(fmaf(a, h, xw));
        hp[t] = cvt_tf32f(h);          // GEMM1 A operand, pre-rounded
    }
    #pragma unroll
    for (int t = TN_; t < TP_; t++) hp[t] = 0.0f;
    if (hidden) hidden[b] = h;          // full precision
}

// ---------------- mma.sync tf32 GEMM ----------------
// C[m,n] = sum_k A[m,k] * B[n,k] + bias[n]
// Tiles: BM=128, BN=128, BK=32. 256 threads = 8 warps (2 m x 4 n), warp tile 64x32.
// smem rows padded to 36 floats -> all fragment LDS conflict-free.
#define ASTR 36
#define AS_FLOATS (128 * ASTR)                 // 4608 per stage
#define SMEM_FLOATS (4 * AS_FLOATS)            // A x2 stages + B x2 stages
#define SMEM_BYTES (SMEM_FLOATS * 4)           // 73728

template<bool RELU, bool GUARDN, bool CVTOUT>
__global__ __launch_bounds__(256, 2)
void gemm_mma(const float* __restrict__ A, int lda,
              const float* __restrict__ Bw, int ldb,
              const float* __restrict__ bias,
              float* __restrict__ C, int ldc, int Nreal, int K)
{
    extern __shared__ float sm[];
    float* As = sm;                 // [2][128][36]
    float* Bs = sm + 2 * AS_FLOATS; // [2][128][36]

    int tid = threadIdx.x;
    int lane = tid & 31;
    int wid  = tid >> 5;
    int wm = wid & 1;               // 0..1 -> 64-row half
    int wn = wid >> 1;              // 0..3 -> 32-col quarter
    int grp = lane >> 2;            // 0..7
    int qk  = lane & 3;             // 0..3
    int m0 = blockIdx.y * 128;
    int n0 = blockIdx.x * 128;

    float acc[4][4][4];
    #pragma unroll
    for (int i = 0; i < 4; i++)
        #pragma unroll
        for (int j = 0; j < 4; j++)
            #pragma unroll
            for (int q = 0; q < 4; q++) acc[i][j][q] = 0.0f;

    const int KT = K >> 5;

    // ---- stage loader: 1024 16B chunks each for A and B ----
    // chunk c: row = c>>3, col16 = c&7  -> global row*ld + col16*4, smem row*36 + col16*4
    #define LOAD_STAGE(kt, s) do {                                                  \
        const float* Ap_ = A  + (size_t)m0 * lda + (kt) * 32;                       \
        const float* Bp_ = Bw + (size_t)n0 * ldb + (kt) * 32;                       \
        float* aS_ = As + (s) * AS_FLOATS;                                          \
        float* bS_ = Bs + (s) * AS_FLOATS;                                          \
        _Pragma("unroll")                                                           \
        for (int i_ = 0; i_ < 4; i_++) {                                            \
            int c_ = i_ * 256 + tid;                                                \
            int r_ = c_ >> 3, co_ = (c_ & 7) << 2;                                  \
            CP16(smem_u32(aS_ + r_ * ASTR + co_), Ap_ + (size_t)r_ * lda + co_);    \
        }                                                                           \
        _Pragma("unroll")                                                           \
        for (int i_ = 0; i_ < 4; i_++) {                                            \
            int c_ = i_ * 256 + tid;                                                \
            int r_ = c_ >> 3, co_ = (c_ & 7) << 2;                                  \
            CP16(smem_u32(bS_ + r_ * ASTR + co_), Bp_ + (size_t)r_ * ldb + co_);    \
        }                                                                           \
        CP_COMMIT();                                                                \
    } while (0)

    LOAD_STAGE(0, 0);

    for (int kt = 0; kt < KT; kt++) {
        int s = kt & 1;
        if (kt + 1 < KT) { LOAD_STAGE(kt + 1, s ^ 1); CP_WAIT1(); }
        else             { CP_WAIT0(); }
        __syncthreads();

        const float* aB = As + s * AS_FLOATS + (wm * 64 + grp) * ASTR;
        const float* bB = Bs + s * AS_FLOATS + (wn * 32 + grp) * ASTR;

        #pragma unroll
        for (int ks = 0; ks < 4; ks++) {
            int kb = ks * 8 + qk;
            uint32_t af[4][4], bf[4][2];
            #pragma unroll
            for (int mt = 0; mt < 4; mt++) {
                const float* p = aB + mt * 16 * ASTR;
                af[mt][0] = __float_as_uint(p[kb]);
                af[mt][1] = __float_as_uint(p[8 * ASTR + kb]);
                af[mt][2] = __float_as_uint(p[kb + 4]);
                af[mt][3] = __float_as_uint(p[8 * ASTR + kb + 4]);
            }
            #pragma unroll
            for (int nt = 0; nt < 4; nt++) {
                const float* p = bB + nt * 8 * ASTR;
                bf[nt][0] = __float_as_uint(p[kb]);
                bf[nt][1] = __float_as_uint(p[kb + 4]);
            }
            #pragma unroll
            for (int mt = 0; mt < 4; mt++)
                #pragma unroll
                for (int nt = 0; nt < 4; nt++)
                    mma_tf32(acc[mt][nt], af[mt], bf[nt]);
        }
        __syncthreads();
    }

    // ---- epilogue ----
    #pragma unroll
    for (int mt = 0; mt < 4; mt++) {
        int r0 = m0 + wm * 64 + mt * 16 + grp;
        #pragma unroll
        for (int nt = 0; nt < 4; nt++) {
            int nc = n0 + wn * 32 + nt * 8 + 2 * qk;
            if (GUARDN && nc >= Nreal) continue;
            float b0 = bias[nc], b1 = bias[nc + 1];
            float v00 = acc[mt][nt][0] + b0, v01 = acc[mt][nt][1] + b1;
            float v10 = acc[mt][nt][2] + b0, v11 = acc[mt][nt][3] + b1;
            if (RELU) {
                v00 = fmaxf(v00, 0.0f); v01 = fmaxf(v01, 0.0f);
                v10 = fmaxf(v10, 0.0f); v11 = fmaxf(v11, 0.0f);
            }
            if (CVTOUT) {
                v00 = cvt_tf32f(v00); v01 = cvt_tf32f(v01);
                v10 = cvt_tf32f(v10); v11 = cvt_tf32f(v11);
            }
            *(float2*)(C + (size_t)r0 * ldc + nc)       = make_float2(v00, v01);
            *(float2*)(C + (size_t)(r0 + 8) * ldc + nc) = make_float2(v10, v11);
        }
    }
}

// ---------------- launcher ----------------
extern "C" void kernel_launch(void* const* d_in, const int* in_sizes, int n_in,
                              void* d_out, int out_size)
{
    const float* x   = (const float*)d_in[0];
    const float* h0  = (const float*)d_in[1];
    const float* Wih = (const float*)d_in[2];
    const float* Whh = (const float*)d_in[3];
    const float* bih = (const float*)d_in[4];
    const float* bhh = (const float*)d_in[5];
    const float* w1  = (const float*)d_in[6];
    const float* b1  = (const float*)d_in[7];
    const float* w2  = (const float*)d_in[8];
    const float* b2  = (const float*)d_in[9];
    const float* w3  = (const float*)d_in[10];
    const float* b3  = (const float*)d_in[11];
    const float* w4  = (const float*)d_in[12];
    const float* b4  = (const float*)d_in[13];
    float* out = (float*)d_out;

    float *hs, *c1, *c2, *c3, *w1c, *w2c, *w3c, *w4c;
    cudaGetSymbolAddress((void**)&hs,  g_hs);
    cudaGetSymbolAddress((void**)&c1,  g_c1);
    cudaGetSymbolAddress((void**)&c2,  g_c2);
    cudaGetSymbolAddress((void**)&c3,  g_c3);
    cudaGetSymbolAddress((void**)&w1c, g_w1c);
    cudaGetSymbolAddress((void**)&w2c, g_w2c);
    cudaGetSymbolAddress((void**)&w3c, g_w3c);
    cudaGetSymbolAddress((void**)&w4c, g_w4c);

    cudaFuncSetAttribute(gemm_mma<true,  false, true >, cudaFuncAttributeMaxDynamicSharedMemorySize, SMEM_BYTES);
    cudaFuncSetAttribute(gemm_mma<false, true,  false>, cudaFuncAttributeMaxDynamicSharedMemorySize, SMEM_BYTES);

    // weight prep (pad + tf32 round)
    wprep_kernel<<<(D1_ * TP_  + 255) / 256, 256>>>(w1, w1c, D1_, TN_, D1_, TP_);
    wprep_kernel<<<(D2_ * D1_  + 255) / 256, 256>>>(w2, w2c, D2_, D1_, D2_, D1_);
    wprep_kernel<<<(D3_ * D2_  + 255) / 256, 256>>>(w3, w3c, D3_, D2_, D3_, D2_);
    wprep_kernel<<<(N4P_ * D3_ + 255) / 256, 256>>>(w4, w4c, TN_, D3_, N4P_, D3_);

    // RNN
    float* hidden = (out_size >= BN_ * TN_ + BN_) ? (out + (size_t)BN_ * TN_) : nullptr;
    rnn_kernel<<<BN_ / 128, 128>>>(x, h0, Wih, Whh, bih, bhh, hs, hidden);

    // GEMM chain on mma.sync tf32
    gemm_mma<true,  false, true ><<<dim3(D1_ / 128, BN_ / 128), 256, SMEM_BYTES>>>(hs, TP_,  w1c, TP_,  b1, c1,  D1_, D1_, TP_);
    gemm_mma<true,  false, true ><<<dim3(D2_ / 128, BN_ / 128), 256, SMEM_BYTES>>>(c1, D1_,  w2c, D1_,  b2, c2,  D2_, D2_, D1_);
    gemm_mma<true,  false, true ><<<dim3(D3_ / 128, BN_ / 128), 256, SMEM_BYTES>>>(c2, D2_,  w3c, D2_,  b3, c3,  D3_, D3_, D2_);
    gemm_mma<false, true,  false><<<dim3(N4P_ / 128, BN_ / 128), 256, SMEM_BYTES>>>(c3, D3_, w4c, D3_,  b4, out, TN_, TN_, D3_);
}

// round 5
// speedup vs baseline: 2.9662x; 1.5087x over previous
#include <cuda_runtime.h>
#include <math.h>
#include <stdint.h>

// ---------------- problem constants ----------------
#define BN_  8192   // batch (GEMM M)
#define TN_  658    // seq len / final out features
#define TP_  672    // K-pad for layer1 (21 * 32)
#define IN_  7
#define D1_  1024
#define D2_  512
#define D3_  128
#define N4P_ 768    // w4 N padded (658 -> 768)

// ---------------- scratch ----------------
__device__ float g_xwT[(size_t)TN_ * BN_];   // [t][b] input projection
__device__ float g_hsT[(size_t)TP_ * BN_];   // [t][b] tf32-rounded, K-padded (A^T of GEMM1)
__device__ float g_c1 [(size_t)BN_ * D1_];
__device__ float g_c2 [(size_t)BN_ * D2_];
__device__ float g_c3 [(size_t)BN_ * D3_];
__device__ float g_w1c[D1_ * TP_];
__device__ float g_w2c[D2_ * D1_];
__device__ float g_w3c[D3_ * D2_];
__device__ float g_w4c[N4P_ * D3_];

// ---------------- helpers ----------------
__device__ __forceinline__ uint32_t smem_u32(const void* p) {
    uint32_t a;
    asm("{ .reg .u64 t; cvta.to.shared.u64 t, %1; cvt.u32.u64 %0, t; }" : "=r"(a) : "l"(p));
    return a;
}
__device__ __forceinline__ float cvt_tf32f(float x) {
    uint32_t u; asm("cvt.rna.tf32.f32 %0, %1;" : "=r"(u) : "f"(x));
    return __uint_as_float(u);
}
#define CP16(sa, ga) asm volatile("cp.async.cg.shared.global [%0], [%1], 16;" :: "r"(sa), "l"(ga))
#define CP_COMMIT()  asm volatile("cp.async.commit_group;" ::: "memory")
#define CP_WAIT0()   asm volatile("cp.async.wait_group 0;" ::: "memory")
#define CP_WAIT1()   asm volatile("cp.async.wait_group 1;" ::: "memory")

__device__ __forceinline__ void mma_tf32(float* d, const uint32_t* a, const uint32_t* b) {
    asm volatile(
        "mma.sync.aligned.m16n8k8.row.col.f32.tf32.tf32.f32 "
        "{%0,%1,%2,%3}, {%4,%5,%6,%7}, {%8,%9}, {%0,%1,%2,%3};"
        : "+f"(d[0]), "+f"(d[1]), "+f"(d[2]), "+f"(d[3])
        : "r"(a[0]), "r"(a[1]), "r"(a[2]), "r"(a[3]), "r"(b[0]), "r"(b[1]));
}

// ---------------- fused weight prep (pad + tf32 round) ----------------
#define WSEG1 (D1_ * TP_)
#define WSEG2 (D2_ * D1_)
#define WSEG3 (D3_ * D2_)
#define WSEG4 (N4P_ * D3_)
#define WTOT  (WSEG1 + WSEG2 + WSEG3 + WSEG4)

__global__ void wprep_all(const float* __restrict__ w1, const float* __restrict__ w2,
                          const float* __restrict__ w3, const float* __restrict__ w4,
                          float* __restrict__ w1c, float* __restrict__ w2c,
                          float* __restrict__ w3c, float* __restrict__ w4c)
{
    int idx = blockIdx.x * blockDim.x + threadIdx.x;
    if (idx < WSEG1) {
        int n = idx / TP_, k = idx - n * TP_;
        w1c[idx] = (k < TN_) ? cvt_tf32f(w1[n * TN_ + k]) : 0.0f;
        return;
    }
    idx -= WSEG1;
    if (idx < WSEG2) { w2c[idx] = cvt_tf32f(w2[idx]); return; }
    idx -= WSEG2;
    if (idx < WSEG3) { w3c[idx] = cvt_tf32f(w3[idx]); return; }
    idx -= WSEG3;
    if (idx < WSEG4) {
        int n = idx / D3_, k = idx - n * D3_;
        w4c[idx] = (n < TN_) ? cvt_tf32f(w4[n * D3_ + k]) : 0.0f;
    }
}

// ---------------- input projection: xwT[t][b] = x[b,t,:]·Wih + bias ----------------
// block = 256 threads, handles 32 consecutive b; loops over 32-t tiles.
// read phase: warp w computes rows r = w+8i, lane -> t (coalesced 896B/warp)
// write phase: warp w writes t-rows w*4+i, lanes -> 32 consecutive b (coalesced 128B)
__global__ __launch_bounds__(256)
void xw_kernel(const float* __restrict__ x,
               const float* __restrict__ Wih,
               const float* __restrict__ bih,
               const float* __restrict__ bhh,
               float* __restrict__ xwT)
{
    __shared__ float sm[32 * 33];
    int tid = threadIdx.x;
    int lane = tid & 31, w = tid >> 5;
    int b0 = blockIdx.x * 32;

    float w0 = Wih[0], w1 = Wih[1], w2 = Wih[2], w3 = Wih[3];
    float w4 = Wih[4], w5 = Wih[5], w6 = Wih[6];
    float bias = bih[0] + bhh[0];

    for (int t0 = 0; t0 < TN_; t0 += 32) {
        #pragma unroll
        for (int rr = 0; rr < 4; rr++) {
            int r = w + rr * 8;
            int t = t0 + lane;
            float v = 0.0f;
            if (t < TN_) {
                const float* p = x + ((size_t)(b0 + r) * TN_ + t) * IN_;
                v = bias;
                v = fmaf(p[0], w0, v);
                v = fmaf(p[1], w1, v);
                v = fmaf(p[2], w2, v);
                v = fmaf(p[3], w3, v);
                v = fmaf(p[4], w4, v);
                v = fmaf(p[5], w5, v);
                v = fmaf(p[6], w6, v);
            }
            sm[lane * 33 + r] = v;
        }
        __syncthreads();
        #pragma unroll
        for (int i = 0; i < 4; i++) {
            int tt = w * 4 + i;
            int t = t0 + tt;
            if (t < TN_) xwT[(size_t)t * BN_ + b0 + lane] = sm[tt * 33 + lane];
        }
        __syncthreads();
    }
}

// ---------------- RNN: pure recurrence, fully coalesced ----------------
__global__ __launch_bounds__(256)
void rnn_kernel(const float* __restrict__ xwT,
                const float* __restrict__ h0,
                const float* __restrict__ Whh,
                float* __restrict__ hsT,
                float* __restrict__ hidden)
{
    int b = blockIdx.x * blockDim.x + threadIdx.x;
    if (b >= BN_) return;
    float a = Whh[0];
    float h = h0[b];
    float nx = xwT[b];
    for (int t = 0; t < TN_; t++) {
        float cur = nx;
        if (t + 1 < TN_) nx = xwT[(size_t)(t + 1) * BN_ + b];
        h = tanhf(fmaf(a, h, cur));
        hsT[(size_t)t * BN_ + b] = cvt_tf32f(h);
    }
    #pragma unroll
    for (int t = TN_; t < TP_; t++) hsT[(size_t)t * BN_ + b] = 0.0f;
    if (hidden) hidden[b] = h;
}

// ---------------- mma.sync tf32 GEMM ----------------
// C[m,n] = sum_k A[m,k]*B[n,k] + bias[n]. BM = MT*32, BN = 128, BK = 32.
// 256 threads = 8 warps (2 m x 4 n), warp tile (MT*16) x 32.
// ATRANS: A given as AT[k][M] (lda = M); smem As [32][136] (conflict-free).
// else:   A row-major [M][K]; smem As [BM][36].
template<int MT, bool ATRANS, bool RELU, bool GUARDN, bool CVTOUT>
__global__ __launch_bounds__(256, 2)
void gemm_mma(const float* __restrict__ A, int lda,
              const float* __restrict__ Bw, int ldb,
              const float* __restrict__ bias,
              float* __restrict__ C, int ldc, int Nreal, int K)
{
    constexpr int BM = MT * 32;
    constexpr int A_STAGE = ATRANS ? 32 * 136 : BM * 36;
    constexpr int B_STAGE = 128 * 36;

    extern __shared__ float sm[];
    float* As = sm;
    float* Bs = sm + 2 * A_STAGE;

    int tid = threadIdx.x;
    int lane = tid & 31;
    int wid  = tid >> 5;
    int wm = wid & 1;
    int wn = wid >> 1;
    int grp = lane >> 2;
    int qk  = lane & 3;
    int m0 = blockIdx.y * BM;
    int n0 = blockIdx.x * 128;

    float acc[MT][4][4];
    #pragma unroll
    for (int i = 0; i < MT; i++)
        #pragma unroll
        for (int j = 0; j < 4; j++)
            #pragma unroll
            for (int q = 0; q < 4; q++) acc[i][j][q] = 0.0f;

    const int KT = K >> 5;

    auto load_stage = [&](int kt, int s) {
        float* aS = As + s * A_STAGE;
        float* bS = Bs + s * B_STAGE;
        if (ATRANS) {
            const float* Ap = A + (size_t)(kt * 32) * lda + m0;
            #pragma unroll
            for (int i = 0; i < 4; i++) {          // 32 rows x 32 chunks
                int c = i * 256 + tid;
                int r = c >> 5, co = (c & 31) << 2;
                CP16(smem_u32(aS + r * 136 + co), Ap + (size_t)r * lda + co);
            }
        } else {
            const float* Ap = A + (size_t)m0 * lda + kt * 32;
            #pragma unroll
            for (int i = 0; i < BM / 32; i++) {    // BM rows x 8 chunks
                int c = i * 256 + tid;
                int r = c >> 3, co = (c & 7) << 2;
                CP16(smem_u32(aS + r * 36 + co), Ap + (size_t)r * lda + co);
            }
        }
        const float* Bp = Bw + (size_t)n0 * ldb + kt * 32;
        #pragma unroll
        for (int i = 0; i < 4; i++) {
            int c = i * 256 + tid;
            int r = c >> 3, co = (c & 7) << 2;
            CP16(smem_u32(bS + r * 36 + co), Bp + (size_t)r * ldb + co);
        }
        CP_COMMIT();
    };

    load_stage(0, 0);

    for (int kt = 0; kt < KT; kt++) {
        int s = kt & 1;
        if (kt + 1 < KT) { load_stage(kt + 1, s ^ 1); CP_WAIT1(); }
        else             { CP_WAIT0(); }
        __syncthreads();

        const float* aS = As + s * A_STAGE;
        const float* aB = aS + (ATRANS ? 0 : (wm * (MT * 16) + grp) * 36);
        const float* bB = Bs + s * B_STAGE + (wn * 32 + grp) * 36;

        #pragma unroll
        for (int ks = 0; ks < 4; ks++) {
            int kb = ks * 8 + qk;
            uint32_t af[MT][4], bf[4][2];
            #pragma unroll
            for (int mt = 0; mt < MT; mt++) {
                if (ATRANS) {
                    int mrow = wm * (MT * 16) + mt * 16 + grp;
                    af[mt][0] = __float_as_uint(aB[kb * 136 + mrow]);
                    af[mt][1] = __float_as_uint(aB[kb * 136 + mrow + 8]);
                    af[mt][2] = __float_as_uint(aB[(kb + 4) * 136 + mrow]);
                    af[mt][3] = __float_as_uint(aB[(kb + 4) * 136 + mrow + 8]);
                } else {
                    const float* p = aB + mt * 16 * 36;
                    af[mt][0] = __float_as_uint(p[kb]);
                    af[mt][1] = __float_as_uint(p[8 * 36 + kb]);
                    af[mt][2] = __float_as_uint(p[kb + 4]);
                    af[mt][3] = __float_as_uint(p[8 * 36 + kb + 4]);
                }
            }
            #pragma unroll
            for (int nt = 0; nt < 4; nt++) {
                const float* p = bB + nt * 8 * 36;
                bf[nt][0] = __float_as_uint(p[kb]);
                bf[nt][1] = __float_as_uint(p[kb + 4]);
            }
            #pragma unroll
            for (int mt = 0; mt < MT; mt++)
                #pragma unroll
                for (int nt = 0; nt < 4; nt++)
                    mma_tf32(acc[mt][nt], af[mt], bf[nt]);
        }
        __syncthreads();
    }

    // ---- epilogue ----
    #pragma unroll
    for (int mt = 0; mt < MT; mt++) {
        int r0 = m0 + wm * (MT * 16) + mt * 16 + grp;
        #pragma unroll
        for (int nt = 0; nt < 4; nt++) {
            int nc = n0 + wn * 32 + nt * 8 + 2 * qk;
            if (GUARDN && nc >= Nreal) continue;
            float b0v = bias[nc], b1v = bias[nc + 1];
            float v00 = acc[mt][nt][0] + b0v, v01 = acc[mt][nt][1] + b1v;
            float v10 = acc[mt][nt][2] + b0v, v11 = acc[mt][nt][3] + b1v;
            if (RELU) {
                v00 = fmaxf(v00, 0.0f); v01 = fmaxf(v01, 0.0f);
                v10 = fmaxf(v10, 0.0f); v11 = fmaxf(v11, 0.0f);
            }
            if (CVTOUT) {
                v00 = cvt_tf32f(v00); v01 = cvt_tf32f(v01);
                v10 = cvt_tf32f(v10); v11 = cvt_tf32f(v11);
            }
            *(float2*)(C + (size_t)r0 * ldc + nc)       = make_float2(v00, v01);
            *(float2*)(C + (size_t)(r0 + 8) * ldc + nc) = make_float2(v10, v11);
        }
    }
}

// ---------------- launcher ----------------
#define SMEM_G1 (2 * (32 * 136 + 128 * 36) * 4)
#define SMEM_G2 (2 * (128 * 36 + 128 * 36) * 4)
#define SMEM_G3 (2 * (64 * 36 + 128 * 36) * 4)

extern "C" void kernel_launch(void* const* d_in, const int* in_sizes, int n_in,
                              void* d_out, int out_size)
{
    const float* x   = (const float*)d_in[0];
    const float* h0  = (const float*)d_in[1];
    const float* Wih = (const float*)d_in[2];
    const float* Whh = (const float*)d_in[3];
    const float* bih = (const float*)d_in[4];
    const float* bhh = (const float*)d_in[5];
    const float* w1  = (const float*)d_in[6];
    const float* b1  = (const float*)d_in[7];
    const float* w2  = (const float*)d_in[8];
    const float* b2  = (const float*)d_in[9];
    const float* w3  = (const float*)d_in[10];
    const float* b3  = (const float*)d_in[11];
    const float* w4  = (const float*)d_in[12];
    const float* b4  = (const float*)d_in[13];
    float* out = (float*)d_out;

    float *xwT, *hsT, *c1, *c2, *c3, *w1c, *w2c, *w3c, *w4c;
    cudaGetSymbolAddress((void**)&xwT, g_xwT);
    cudaGetSymbolAddress((void**)&hsT, g_hsT);
    cudaGetSymbolAddress((void**)&c1,  g_c1);
    cudaGetSymbolAddress((void**)&c2,  g_c2);
    cudaGetSymbolAddress((void**)&c3,  g_c3);
    cudaGetSymbolAddress((void**)&w1c, g_w1c);
    cudaGetSymbolAddress((void**)&w2c, g_w2c);
    cudaGetSymbolAddress((void**)&w3c, g_w3c);
    cudaGetSymbolAddress((void**)&w4c, g_w4c);

    cudaFuncSetAttribute(gemm_mma<4, true,  true,  false, true >, cudaFuncAttributeMaxDynamicSharedMemorySize, SMEM_G1);
    cudaFuncSetAttribute(gemm_mma<4, false, true,  false, true >, cudaFuncAttributeMaxDynamicSharedMemorySize, SMEM_G2);
    cudaFuncSetAttribute(gemm_mma<2, false, true,  false, true >, cudaFuncAttributeMaxDynamicSharedMemorySize, SMEM_G3);
    cudaFuncSetAttribute(gemm_mma<4, false, false, true,  false>, cudaFuncAttributeMaxDynamicSharedMemorySize, SMEM_G2);

    // weight prep (single fused launch)
    wprep_all<<<(WTOT + 255) / 256, 256>>>(w1, w2, w3, w4, w1c, w2c, w3c, w4c);

    // input projection, then pure recurrence (both fully coalesced)
    xw_kernel<<<BN_ / 32, 256>>>(x, Wih, bih, bhh, xwT);
    float* hidden = (out_size >= BN_ * TN_ + BN_) ? (out + (size_t)BN_ * TN_) : nullptr;
    rnn_kernel<<<BN_ / 256, 256>>>(xwT, h0, Whh, hsT, hidden);

    // GEMM chain on mma.sync tf32
    gemm_mma<4, true,  true,  false, true ><<<dim3(D1_ / 128, BN_ / 128), 256, SMEM_G1>>>(hsT, BN_, w1c, TP_,  b1, c1,  D1_, D1_, TP_);
    gemm_mma<4, false, true,  false, true ><<<dim3(D2_ / 128, BN_ / 128), 256, SMEM_G2>>>(c1,  D1_, w2c, D1_,  b2, c2,  D2_, D2_, D1_);
    gemm_mma<2, false, true,  false, true ><<<dim3(D3_ / 128, BN_ / 64 ), 256, SMEM_G3>>>(c2,  D2_, w3c, D2_,  b3, c3,  D3_, D3_, D2_);
    gemm_mma<4, false, false, true,  false><<<dim3(N4P_ / 128, BN_ / 128), 256, SMEM_G2>>>(c3,  D3_, w4c, D3_,  b4, out, TN_, TN_, D3_);
}